// round 2
// baseline (speedup 1.0000x reference)
#include <cuda_runtime.h>
#include <math.h>

// Problem constants
#define B_   2
#define S_   2048
#define D_   1024
#define H_   16
#define E_   64
#define HE_  1024          // H_*E_
#define MR_  4096          // B_*S_

// ---------------- scratch (device globals; allocation-free rule) ----------------
__device__ float g_Wt[3 * D_ * HE_];                    // transposed weights [3][D][H*E]
__device__ float g_Q[MR_ * HE_];                        // [B,S,H*E]
__device__ float g_K[MR_ * HE_];
__device__ float g_V[MR_ * HE_];
__device__ float g_S[(size_t)B_ * H_ * S_ * S_];        // scores^T [bh][t][s]  (537 MB)
__device__ float g_m [B_ * H_ * S_];                    // per-(bh,t) max over s
__device__ float g_il[B_ * H_ * S_];                    // per-(bh,t) 1/sumexp
__device__ float g_Hd[MR_ * HE_];                       // heads in [B,S,H*E]

// ---------------- weight transpose: w[h][d][e] -> Wt[d][h*E+e] ----------------
__global__ __launch_bounds__(256) void transpose_w(const float* __restrict__ wq,
                                                   const float* __restrict__ wk,
                                                   const float* __restrict__ wv) {
    int idx = blockIdx.x * 256 + threadIdx.x;   // over H*D*E = 1M
    int e = idx & 63;
    int d = (idx >> 6) & 1023;
    int h = idx >> 16;
    int dst = d * HE_ + h * E_ + e;
    g_Wt[dst]               = wq[idx];
    g_Wt[D_ * HE_ + dst]    = wk[idx];
    g_Wt[2 * D_ * HE_ + dst] = wv[idx];
}

// ---------------- SGEMM NN: C[M,N] = A[M,K] @ B[K,N], all row-major ----------------
// BM=BN=128, BK=8, 256 threads, 8x8 per-thread tile. Dims assumed divisible.
__global__ __launch_bounds__(256) void sgemm_nn_128(const float* __restrict__ A,
                                                    const float* __restrict__ B,
                                                    float* __restrict__ C,
                                                    int M, int N, int K) {
    __shared__ float As[8][128];
    __shared__ float Bs[8][128];
    const int tid  = threadIdx.x;
    const int row0 = blockIdx.y * 128;
    const int col0 = blockIdx.x * 128;
    const int trow = (tid >> 4) * 8;
    const int tcol = (tid & 15) * 8;
    const int a_row = tid >> 1;
    const int a_col = (tid & 1) * 4;
    const int b_row = tid >> 5;
    const int b_col = (tid & 31) * 4;
    const float* Ap = A + (size_t)(row0 + a_row) * K + a_col;
    const float* Bp = B + (size_t)b_row * N + col0 + b_col;

    float acc[8][8];
#pragma unroll
    for (int i = 0; i < 8; i++)
#pragma unroll
        for (int j = 0; j < 8; j++) acc[i][j] = 0.f;

    for (int k0 = 0; k0 < K; k0 += 8) {
        float4 av = *(const float4*)(Ap + k0);
        As[a_col + 0][a_row] = av.x;
        As[a_col + 1][a_row] = av.y;
        As[a_col + 2][a_row] = av.z;
        As[a_col + 3][a_row] = av.w;
        float4 bv = *(const float4*)(Bp + (size_t)k0 * N);
        *(float4*)&Bs[b_row][b_col] = bv;
        __syncthreads();
#pragma unroll
        for (int kk = 0; kk < 8; kk++) {
            float4 a0 = *(const float4*)&As[kk][trow];
            float4 a1 = *(const float4*)&As[kk][trow + 4];
            float4 b0 = *(const float4*)&Bs[kk][tcol];
            float4 b1 = *(const float4*)&Bs[kk][tcol + 4];
            float ar[8] = {a0.x, a0.y, a0.z, a0.w, a1.x, a1.y, a1.z, a1.w};
            float br[8] = {b0.x, b0.y, b0.z, b0.w, b1.x, b1.y, b1.z, b1.w};
#pragma unroll
            for (int i = 0; i < 8; i++)
#pragma unroll
                for (int j = 0; j < 8; j++)
                    acc[i][j] = fmaf(ar[i], br[j], acc[i][j]);
        }
        __syncthreads();
    }
#pragma unroll
    for (int i = 0; i < 8; i++) {
        float* Cp = C + (size_t)(row0 + trow + i) * N + col0 + tcol;
        *(float4*)Cp       = make_float4(acc[i][0], acc[i][1], acc[i][2], acc[i][3]);
        *(float4*)(Cp + 4) = make_float4(acc[i][4], acc[i][5], acc[i][6], acc[i][7]);
    }
}

// ---------------- scores^T: S[bh][t][s] = (1/8) * sum_e K[t,e] * Q[s,e] ----------------
// NT GEMM per (b,h): A=K rows (ld=HE_), B=Q rows (ld=HE_), K-dim = 64.
__global__ __launch_bounds__(256) void scores_nt(const float* __restrict__ Kin,
                                                 const float* __restrict__ Qin,
                                                 float* __restrict__ Sout) {
    const int bh = blockIdx.z;
    const int b = bh >> 4, h = bh & 15;
    const float* Ab = Kin + (size_t)b * S_ * HE_ + h * E_;
    const float* Bb = Qin + (size_t)b * S_ * HE_ + h * E_;
    float* Cb = Sout + (size_t)bh * S_ * S_;
    const int t0 = blockIdx.y * 128;
    const int s0 = blockIdx.x * 128;
    __shared__ float As[16][128];   // [e][t]
    __shared__ float Bs[16][128];   // [e][s]
    const int tid  = threadIdx.x;
    const int trow = (tid >> 4) * 8;   // t direction
    const int tcol = (tid & 15) * 8;   // s direction

    float acc[8][8];
#pragma unroll
    for (int i = 0; i < 8; i++)
#pragma unroll
        for (int j = 0; j < 8; j++) acc[i][j] = 0.f;

    for (int e0 = 0; e0 < E_; e0 += 16) {
#pragma unroll
        for (int j = 0; j < 2; j++) {
            int f  = j * 256 + tid;
            int r  = f >> 2;             // 0..127
            int c4 = (f & 3) * 4;        // 0,4,8,12
            float4 av = *(const float4*)(Ab + (size_t)(t0 + r) * HE_ + e0 + c4);
            As[c4 + 0][r] = av.x; As[c4 + 1][r] = av.y;
            As[c4 + 2][r] = av.z; As[c4 + 3][r] = av.w;
            float4 bv = *(const float4*)(Bb + (size_t)(s0 + r) * HE_ + e0 + c4);
            Bs[c4 + 0][r] = bv.x; Bs[c4 + 1][r] = bv.y;
            Bs[c4 + 2][r] = bv.z; Bs[c4 + 3][r] = bv.w;
        }
        __syncthreads();
#pragma unroll
        for (int kk = 0; kk < 16; kk++) {
            float4 a0 = *(const float4*)&As[kk][trow];
            float4 a1 = *(const float4*)&As[kk][trow + 4];
            float4 b0 = *(const float4*)&Bs[kk][tcol];
            float4 b1 = *(const float4*)&Bs[kk][tcol + 4];
            float ar[8] = {a0.x, a0.y, a0.z, a0.w, a1.x, a1.y, a1.z, a1.w};
            float br[8] = {b0.x, b0.y, b0.z, b0.w, b1.x, b1.y, b1.z, b1.w};
#pragma unroll
            for (int i = 0; i < 8; i++)
#pragma unroll
                for (int j = 0; j < 8; j++)
                    acc[i][j] = fmaf(ar[i], br[j], acc[i][j]);
        }
        __syncthreads();
    }
#pragma unroll
    for (int i = 0; i < 8; i++) {
        float* Cp = Cb + (size_t)(t0 + trow + i) * S_ + s0 + tcol;
        *(float4*)Cp = make_float4(acc[i][0] * 0.125f, acc[i][1] * 0.125f,
                                   acc[i][2] * 0.125f, acc[i][3] * 0.125f);
        *(float4*)(Cp + 4) = make_float4(acc[i][4] * 0.125f, acc[i][5] * 0.125f,
                                         acc[i][6] * 0.125f, acc[i][7] * 0.125f);
    }
}

// ---------------- per-row (fixed t) softmax stats over contiguous s ----------------
__global__ __launch_bounds__(256) void softmax_stats(const float* __restrict__ Sin,
                                                     float* __restrict__ mrow,
                                                     float* __restrict__ ilrow) {
    const int row = blockIdx.x;                     // bh*S_ + t
    const float* p = Sin + (size_t)row * S_;
    const int tid = threadIdx.x;
    __shared__ float red[256];

    float mx = -3.4e38f;
    for (int i = tid * 4; i < S_; i += 1024) {
        float4 v = *(const float4*)(p + i);
        mx = fmaxf(mx, fmaxf(fmaxf(v.x, v.y), fmaxf(v.z, v.w)));
    }
    red[tid] = mx;
    __syncthreads();
    for (int s = 128; s > 0; s >>= 1) {
        if (tid < s) red[tid] = fmaxf(red[tid], red[tid + s]);
        __syncthreads();
    }
    mx = red[0];
    __syncthreads();

    float sum = 0.f;
    for (int i = tid * 4; i < S_; i += 1024) {
        float4 v = *(const float4*)(p + i);
        sum += expf(v.x - mx) + expf(v.y - mx) + expf(v.z - mx) + expf(v.w - mx);
    }
    red[tid] = sum;
    __syncthreads();
    for (int s = 128; s > 0; s >>= 1) {
        if (tid < s) red[tid] += red[tid + s];
        __syncthreads();
    }
    if (tid == 0) { mrow[row] = mx; ilrow[row] = 1.0f / red[0]; }
}

// ---------------- heads: Hd[b,s,h*E+e] = sum_t exp(S[t,s]-m[t])*il[t] * V[t,e] ----------------
// TN GEMM with softmax fused into the A-tile load. N=E_=64 fits one block column,
// so every score element is read+exp'd exactly once.
__global__ __launch_bounds__(256) void av_exp_tn(const float* __restrict__ Sin,
                                                 const float* __restrict__ mrow,
                                                 const float* __restrict__ ilrow,
                                                 const float* __restrict__ Vin,
                                                 float* __restrict__ Hd) {
    const int bh = blockIdx.y;
    const int b = bh >> 4, h = bh & 15;
    const float* Sb = Sin + (size_t)bh * S_ * S_;
    const float* mb = mrow + bh * S_;
    const float* ib = ilrow + bh * S_;
    const float* Vb = Vin + (size_t)b * S_ * HE_ + h * E_;
    float* Cb = Hd + (size_t)b * S_ * HE_ + h * E_;
    const int s0 = blockIdx.x * 128;
    __shared__ float Ps[16][128];   // [t][s]  (probabilities)
    __shared__ float Vs[16][64];    // [t][e]
    const int tid  = threadIdx.x;
    const int trow = (tid >> 4) * 8;   // s direction
    const int tcol = (tid & 15) * 4;   // e direction

    float acc[8][4];
#pragma unroll
    for (int i = 0; i < 8; i++)
#pragma unroll
        for (int j = 0; j < 4; j++) acc[i][j] = 0.f;

    for (int t0 = 0; t0 < S_; t0 += 16) {
#pragma unroll
        for (int j = 0; j < 2; j++) {
            int f  = j * 256 + tid;
            int r  = f >> 5;             // 0..15
            int c4 = (f & 31) * 4;       // 0..124
            int t  = t0 + r;
            float mv = mb[t];
            float iv = ib[t];
            float4 sv = *(const float4*)(Sb + (size_t)t * S_ + s0 + c4);
            Ps[r][c4 + 0] = expf(sv.x - mv) * iv;
            Ps[r][c4 + 1] = expf(sv.y - mv) * iv;
            Ps[r][c4 + 2] = expf(sv.z - mv) * iv;
            Ps[r][c4 + 3] = expf(sv.w - mv) * iv;
        }
        {
            int r  = tid >> 4;           // 0..15
            int c4 = (tid & 15) * 4;     // 0..60
            *(float4*)&Vs[r][c4] = *(const float4*)(Vb + (size_t)(t0 + r) * HE_ + c4);
        }
        __syncthreads();
#pragma unroll
        for (int kk = 0; kk < 16; kk++) {
            float4 a0 = *(const float4*)&Ps[kk][trow];
            float4 a1 = *(const float4*)&Ps[kk][trow + 4];
            float4 bv = *(const float4*)&Vs[kk][tcol];
            float ar[8] = {a0.x, a0.y, a0.z, a0.w, a1.x, a1.y, a1.z, a1.w};
            float br[4] = {bv.x, bv.y, bv.z, bv.w};
#pragma unroll
            for (int i = 0; i < 8; i++)
#pragma unroll
                for (int j = 0; j < 4; j++)
                    acc[i][j] = fmaf(ar[i], br[j], acc[i][j]);
        }
        __syncthreads();
    }
#pragma unroll
    for (int i = 0; i < 8; i++) {
        *(float4*)(Cb + (size_t)(s0 + trow + i) * HE_ + tcol) =
            make_float4(acc[i][0], acc[i][1], acc[i][2], acc[i][3]);
    }
}

// ---------------- launch ----------------
extern "C" void kernel_launch(void* const* d_in, const int* in_sizes, int n_in,
                              void* d_out, int out_size) {
    const float* x    = (const float*)d_in[0];
    // d_in[1] = attention_mask (unused, as in the reference)
    const float* wq   = (const float*)d_in[2];
    const float* wk   = (const float*)d_in[3];
    const float* wv   = (const float*)d_in[4];
    const float* wagg = (const float*)d_in[5];
    float* out = (float*)d_out;

    float *pWt, *pQ, *pK, *pV, *pS, *pm, *pil, *pHd;
    cudaGetSymbolAddress((void**)&pWt, g_Wt);
    cudaGetSymbolAddress((void**)&pQ,  g_Q);
    cudaGetSymbolAddress((void**)&pK,  g_K);
    cudaGetSymbolAddress((void**)&pV,  g_V);
    cudaGetSymbolAddress((void**)&pS,  g_S);
    cudaGetSymbolAddress((void**)&pm,  g_m);
    cudaGetSymbolAddress((void**)&pil, g_il);
    cudaGetSymbolAddress((void**)&pHd, g_Hd);

    // 1) transpose weights to [D, H*E]
    transpose_w<<<(H_ * D_ * E_) / 256, 256>>>(wq, wk, wv);

    // 2) QKV projections: [4096,1024] @ [1024,1024]
    dim3 gProj(HE_ / 128, MR_ / 128);   // (8, 32)
    sgemm_nn_128<<<gProj, 256>>>(x, pWt,                pQ, MR_, HE_, D_);
    sgemm_nn_128<<<gProj, 256>>>(x, pWt + D_ * HE_,     pK, MR_, HE_, D_);
    sgemm_nn_128<<<gProj, 256>>>(x, pWt + 2 * D_ * HE_, pV, MR_, HE_, D_);

    // 3) scores^T (stored [t][s] so softmax groups are contiguous)
    scores_nt<<<dim3(S_ / 128, S_ / 128, B_ * H_), 256>>>(pK, pQ, pS);

    // 4) per-(bh,t) max + 1/sumexp
    softmax_stats<<<B_ * H_ * S_, 256>>>(pS, pm, pil);

    // 5) heads = attn @ v with fused exp-normalize
    av_exp_tn<<<dim3(S_ / 128, B_ * H_), 256>>>(pS, pm, pil, pV, pHd);

    // 6) output = heads @ w_agg
    sgemm_nn_128<<<dim3(D_ / 128, MR_ / 128), 256>>>(pHd, wagg, out, MR_, D_, D_);
}

// round 17
// speedup vs baseline: 1.0750x; 1.0750x over previous
#include <cuda_runtime.h>
#include <math.h>

// Problem constants
#define B_   2
#define S_   2048
#define D_   1024
#define H_   16
#define E_   64
#define HE_  1024          // H_*E_
#define MR_  4096          // B_*S_

typedef unsigned long long u64;

// ---- packed fp32x2 helpers (sm_100+; FFMA2 is PTX-only) ----
__device__ __forceinline__ u64 pack2(float x) {
    u64 r; asm("mov.b64 %0, {%1, %1};" : "=l"(r) : "f"(x)); return r;
}
__device__ __forceinline__ void fma2(u64 &d, u64 a, u64 b) {
    asm("fma.rn.f32x2 %0, %1, %2, %0;" : "+l"(d) : "l"(a), "l"(b));
}
__device__ __forceinline__ float2 unpack2(u64 v) {
    float2 r; asm("mov.b64 {%0, %1}, %2;" : "=f"(r.x), "=f"(r.y) : "l"(v)); return r;
}

// ---------------- scratch (device globals; allocation-free rule) ----------------
__device__ float g_Wt[3 * D_ * HE_];                    // transposed weights [3][D][H*E]
__device__ float g_Q[MR_ * HE_];
__device__ float g_K[MR_ * HE_];
__device__ float g_V[MR_ * HE_];
__device__ float g_S[(size_t)B_ * H_ * S_ * S_];        // scores^T [bh][t][s]
__device__ float g_m [B_ * H_ * S_];
__device__ float g_il[B_ * H_ * S_];
__device__ float g_Hd[MR_ * HE_];

// ---------------- weight transpose: w[h][d][e] -> Wt[d][h*E+e] ----------------
__global__ __launch_bounds__(256) void transpose_w(const float* __restrict__ wq,
                                                   const float* __restrict__ wk,
                                                   const float* __restrict__ wv) {
    int idx = blockIdx.x * 256 + threadIdx.x;
    int e = idx & 63;
    int d = (idx >> 6) & 1023;
    int h = idx >> 16;
    int dst = d * HE_ + h * E_ + e;
    g_Wt[dst]                = wq[idx];
    g_Wt[D_ * HE_ + dst]     = wk[idx];
    g_Wt[2 * D_ * HE_ + dst] = wv[idx];
}

// ---------------- SGEMM NN, double-buffered, f32x2 ----------------
// C[M,N] = A[M,K] @ B[K,N]; BM=BN=128, BK=8, 256 threads, 8x8/thread.
__global__ __launch_bounds__(256, 2) void sgemm_nn_128(const float* __restrict__ A,
                                                       const float* __restrict__ B,
                                                       float* __restrict__ C,
                                                       int M, int N, int K) {
    __shared__ __align__(16) float As[2][8][128];
    __shared__ __align__(16) float Bs[2][8][128];
    const int tid  = threadIdx.x;
    const int row0 = blockIdx.y * 128;
    const int col0 = blockIdx.x * 128;
    const int trow = (tid >> 4) * 8;
    const int tcol = (tid & 15) * 8;
    const int a_row = tid >> 1;
    const int a_col = (tid & 1) * 4;
    const int b_row = tid >> 5;
    const int b_col = (tid & 31) * 4;
    const float* Ap = A + (size_t)(row0 + a_row) * K + a_col;
    const float* Bp = B + (size_t)b_row * N + col0 + b_col;

    u64 acc[8][4];
#pragma unroll
    for (int i = 0; i < 8; i++)
#pragma unroll
        for (int j = 0; j < 4; j++) acc[i][j] = 0ull;

    const int T = K >> 3;
    // prefetch tile 0
    float4 av = *(const float4*)(Ap);
    float4 bv = *(const float4*)(Bp);
    As[0][a_col + 0][a_row] = av.x;
    As[0][a_col + 1][a_row] = av.y;
    As[0][a_col + 2][a_row] = av.z;
    As[0][a_col + 3][a_row] = av.w;
    *(float4*)&Bs[0][b_row][b_col] = bv;
    __syncthreads();

    int buf = 0;
    for (int t = 0; t < T; t++) {
        if (t + 1 < T) {
            int k0 = (t + 1) << 3;
            av = *(const float4*)(Ap + k0);
            bv = *(const float4*)(Bp + (size_t)k0 * N);
        }
#pragma unroll
        for (int kk = 0; kk < 8; kk++) {
            ulonglong2 bA = *(const ulonglong2*)&Bs[buf][kk][tcol];
            ulonglong2 bB = *(const ulonglong2*)&Bs[buf][kk][tcol + 4];
            float4 a0 = *(const float4*)&As[buf][kk][trow];
            float4 a1 = *(const float4*)&As[buf][kk][trow + 4];
            u64 ap[8] = {pack2(a0.x), pack2(a0.y), pack2(a0.z), pack2(a0.w),
                         pack2(a1.x), pack2(a1.y), pack2(a1.z), pack2(a1.w)};
#pragma unroll
            for (int i = 0; i < 8; i++) {
                fma2(acc[i][0], ap[i], bA.x);
                fma2(acc[i][1], ap[i], bA.y);
                fma2(acc[i][2], ap[i], bB.x);
                fma2(acc[i][3], ap[i], bB.y);
            }
        }
        if (t + 1 < T) {
            int nb = buf ^ 1;
            As[nb][a_col + 0][a_row] = av.x;
            As[nb][a_col + 1][a_row] = av.y;
            As[nb][a_col + 2][a_row] = av.z;
            As[nb][a_col + 3][a_row] = av.w;
            *(float4*)&Bs[nb][b_row][b_col] = bv;
        }
        __syncthreads();
        buf ^= 1;
    }

#pragma unroll
    for (int i = 0; i < 8; i++) {
        float* Cp = C + (size_t)(row0 + trow + i) * N + col0 + tcol;
        float2 c0 = unpack2(acc[i][0]);
        float2 c1 = unpack2(acc[i][1]);
        float2 c2 = unpack2(acc[i][2]);
        float2 c3 = unpack2(acc[i][3]);
        *(float4*)Cp       = make_float4(c0.x, c0.y, c1.x, c1.y);
        *(float4*)(Cp + 4) = make_float4(c2.x, c2.y, c3.x, c3.y);
    }
}

// ---------------- scores^T: S[bh][t][s] = (1/8) * sum_e K[t,e] * Q[s,e] ----------------
// NT GEMM per (b,h), double-buffered BK=16, f32x2.
__global__ __launch_bounds__(256, 2) void scores_nt(const float* __restrict__ Kin,
                                                    const float* __restrict__ Qin,
                                                    float* __restrict__ Sout) {
    const int bh = blockIdx.z;
    const int b = bh >> 4, h = bh & 15;
    const float* Ab = Kin + (size_t)b * S_ * HE_ + h * E_;
    const float* Bb = Qin + (size_t)b * S_ * HE_ + h * E_;
    float* Cb = Sout + (size_t)bh * S_ * S_;
    const int t0 = blockIdx.y * 128;
    const int s0 = blockIdx.x * 128;
    __shared__ __align__(16) float As[2][16][128];   // [e][t]
    __shared__ __align__(16) float Bs[2][16][128];   // [e][s]
    const int tid  = threadIdx.x;
    const int trow = (tid >> 4) * 8;
    const int tcol = (tid & 15) * 8;
    // load mapping (per 16-e tile): 2 chunks per thread
    const int r0l = tid >> 2;                 // 0..63 (j=0), +64 (j=1)
    const int c4l = (tid & 3) * 4;            // 0,4,8,12

    u64 acc[8][4];
#pragma unroll
    for (int i = 0; i < 8; i++)
#pragma unroll
        for (int j = 0; j < 4; j++) acc[i][j] = 0ull;

    float4 sa[2], sb[2];
    // prefetch e-tile 0
#pragma unroll
    for (int j = 0; j < 2; j++) {
        int r = r0l + j * 64;
        sa[j] = *(const float4*)(Ab + (size_t)(t0 + r) * HE_ + c4l);
        sb[j] = *(const float4*)(Bb + (size_t)(s0 + r) * HE_ + c4l);
    }
#pragma unroll
    for (int j = 0; j < 2; j++) {
        int r = r0l + j * 64;
        As[0][c4l + 0][r] = sa[j].x; As[0][c4l + 1][r] = sa[j].y;
        As[0][c4l + 2][r] = sa[j].z; As[0][c4l + 3][r] = sa[j].w;
        Bs[0][c4l + 0][r] = sb[j].x; Bs[0][c4l + 1][r] = sb[j].y;
        Bs[0][c4l + 2][r] = sb[j].z; Bs[0][c4l + 3][r] = sb[j].w;
    }
    __syncthreads();

    int buf = 0;
    for (int t = 0; t < 4; t++) {             // E_/16 = 4 tiles
        if (t + 1 < 4) {
            int e0 = (t + 1) * 16;
#pragma unroll
            for (int j = 0; j < 2; j++) {
                int r = r0l + j * 64;
                sa[j] = *(const float4*)(Ab + (size_t)(t0 + r) * HE_ + e0 + c4l);
                sb[j] = *(const float4*)(Bb + (size_t)(s0 + r) * HE_ + e0 + c4l);
            }
        }
#pragma unroll
        for (int kk = 0; kk < 16; kk++) {
            ulonglong2 bA = *(const ulonglong2*)&Bs[buf][kk][tcol];
            ulonglong2 bB = *(const ulonglong2*)&Bs[buf][kk][tcol + 4];
            float4 a0 = *(const float4*)&As[buf][kk][trow];
            float4 a1 = *(const float4*)&As[buf][kk][trow + 4];
            u64 ap[8] = {pack2(a0.x), pack2(a0.y), pack2(a0.z), pack2(a0.w),
                         pack2(a1.x), pack2(a1.y), pack2(a1.z), pack2(a1.w)};
#pragma unroll
            for (int i = 0; i < 8; i++) {
                fma2(acc[i][0], ap[i], bA.x);
                fma2(acc[i][1], ap[i], bA.y);
                fma2(acc[i][2], ap[i], bB.x);
                fma2(acc[i][3], ap[i], bB.y);
            }
        }
        if (t + 1 < 4) {
            int nb = buf ^ 1;
#pragma unroll
            for (int j = 0; j < 2; j++) {
                int r = r0l + j * 64;
                As[nb][c4l + 0][r] = sa[j].x; As[nb][c4l + 1][r] = sa[j].y;
                As[nb][c4l + 2][r] = sa[j].z; As[nb][c4l + 3][r] = sa[j].w;
                Bs[nb][c4l + 0][r] = sb[j].x; Bs[nb][c4l + 1][r] = sb[j].y;
                Bs[nb][c4l + 2][r] = sb[j].z; Bs[nb][c4l + 3][r] = sb[j].w;
            }
        }
        __syncthreads();
        buf ^= 1;
    }

#pragma unroll
    for (int i = 0; i < 8; i++) {
        float* Cp = Cb + (size_t)(t0 + trow + i) * S_ + s0 + tcol;
        float2 c0 = unpack2(acc[i][0]);
        float2 c1 = unpack2(acc[i][1]);
        float2 c2 = unpack2(acc[i][2]);
        float2 c3 = unpack2(acc[i][3]);
        *(float4*)Cp       = make_float4(c0.x * 0.125f, c0.y * 0.125f, c1.x * 0.125f, c1.y * 0.125f);
        *(float4*)(Cp + 4) = make_float4(c2.x * 0.125f, c2.y * 0.125f, c3.x * 0.125f, c3.y * 0.125f);
    }
}

// ---------------- per-row (fixed t) softmax stats over contiguous s ----------------
__global__ __launch_bounds__(256) void softmax_stats(const float* __restrict__ Sin,
                                                     float* __restrict__ mrow,
                                                     float* __restrict__ ilrow) {
    const int row = blockIdx.x;
    const float* p = Sin + (size_t)row * S_;
    const int tid = threadIdx.x;
    __shared__ float red[256];

    float mx = -3.4e38f;
    for (int i = tid * 4; i < S_; i += 1024) {
        float4 v = *(const float4*)(p + i);
        mx = fmaxf(mx, fmaxf(fmaxf(v.x, v.y), fmaxf(v.z, v.w)));
    }
    red[tid] = mx;
    __syncthreads();
    for (int s = 128; s > 0; s >>= 1) {
        if (tid < s) red[tid] = fmaxf(red[tid], red[tid + s]);
        __syncthreads();
    }
    mx = red[0];
    __syncthreads();

    float sum = 0.f;
    for (int i = tid * 4; i < S_; i += 1024) {
        float4 v = *(const float4*)(p + i);
        sum += expf(v.x - mx) + expf(v.y - mx) + expf(v.z - mx) + expf(v.w - mx);
    }
    red[tid] = sum;
    __syncthreads();
    for (int s = 128; s > 0; s >>= 1) {
        if (tid < s) red[tid] += red[tid + s];
        __syncthreads();
    }
    if (tid == 0) { mrow[row] = mx; ilrow[row] = 1.0f / red[0]; }
}

// ---------------- heads: Hd[b,s,h*E+e] = sum_t softmax * V[t,e] ----------------
// 128 threads, 8x8 per-thread tile (s x e), f32x2, exp fused into A-tile load.
__global__ __launch_bounds__(128) void av_exp_tn(const float* __restrict__ Sin,
                                                 const float* __restrict__ mrow,
                                                 const float* __restrict__ ilrow,
                                                 const float* __restrict__ Vin,
                                                 float* __restrict__ Hd) {
    const int bh = blockIdx.y;
    const int b = bh >> 4, h = bh & 15;
    const float* Sb = Sin + (size_t)bh * S_ * S_;
    const float* mb = mrow + bh * S_;
    const float* ib = ilrow + bh * S_;
    const float* Vb = Vin + (size_t)b * S_ * HE_ + h * E_;
    float* Cb = Hd + (size_t)b * S_ * HE_ + h * E_;
    const int s0 = blockIdx.x * 128;
    __shared__ __align__(16) float Ps[16][128];   // [t][s]
    __shared__ __align__(16) float Vs[16][64];    // [t][e]
    const int tid  = threadIdx.x;
    const int trow = (tid >> 3) * 8;   // s: 16 groups x 8
    const int tcol = (tid & 7) * 8;    // e: 8 groups x 8

    u64 acc[8][4];
#pragma unroll
    for (int i = 0; i < 8; i++)
#pragma unroll
        for (int j = 0; j < 4; j++) acc[i][j] = 0ull;

    for (int t0 = 0; t0 < S_; t0 += 16) {
        // Ps fill: 16x128 probabilities (each element exp'd exactly once overall)
#pragma unroll
        for (int it = 0; it < 4; it++) {
            int idx = it * 512 + tid * 4;
            int r = idx >> 7, c = idx & 127;
            int t = t0 + r;
            float mv = mb[t];
            float iv = ib[t];
            float4 sv = *(const float4*)(Sb + (size_t)t * S_ + s0 + c);
            Ps[r][c + 0] = expf(sv.x - mv) * iv;
            Ps[r][c + 1] = expf(sv.y - mv) * iv;
            Ps[r][c + 2] = expf(sv.z - mv) * iv;
            Ps[r][c + 3] = expf(sv.w - mv) * iv;
        }
        // Vs fill: 16x64
#pragma unroll
        for (int it = 0; it < 2; it++) {
            int idx = it * 512 + tid * 4;
            int r = idx >> 6, c = idx & 63;
            *(float4*)&Vs[r][c] = *(const float4*)(Vb + (size_t)(t0 + r) * HE_ + c);
        }
        __syncthreads();
#pragma unroll
        for (int kk = 0; kk < 16; kk++) {
            ulonglong2 bA = *(const ulonglong2*)&Vs[kk][tcol];
            ulonglong2 bB = *(const ulonglong2*)&Vs[kk][tcol + 4];
            float4 a0 = *(const float4*)&Ps[kk][trow];
            float4 a1 = *(const float4*)&Ps[kk][trow + 4];
            u64 ap[8] = {pack2(a0.x), pack2(a0.y), pack2(a0.z), pack2(a0.w),
                         pack2(a1.x), pack2(a1.y), pack2(a1.z), pack2(a1.w)};
#pragma unroll
            for (int i = 0; i < 8; i++) {
                fma2(acc[i][0], ap[i], bA.x);
                fma2(acc[i][1], ap[i], bA.y);
                fma2(acc[i][2], ap[i], bB.x);
                fma2(acc[i][3], ap[i], bB.y);
            }
        }
        __syncthreads();
    }

#pragma unroll
    for (int i = 0; i < 8; i++) {
        float* Cp = Cb + (size_t)(s0 + trow + i) * HE_ + tcol;
        float2 c0 = unpack2(acc[i][0]);
        float2 c1 = unpack2(acc[i][1]);
        float2 c2 = unpack2(acc[i][2]);
        float2 c3 = unpack2(acc[i][3]);
        *(float4*)Cp       = make_float4(c0.x, c0.y, c1.x, c1.y);
        *(float4*)(Cp + 4) = make_float4(c2.x, c2.y, c3.x, c3.y);
    }
}

// ---------------- launch ----------------
extern "C" void kernel_launch(void* const* d_in, const int* in_sizes, int n_in,
                              void* d_out, int out_size) {
    const float* x    = (const float*)d_in[0];
    // d_in[1] = attention_mask (unused, as in the reference)
    const float* wq   = (const float*)d_in[2];
    const float* wk   = (const float*)d_in[3];
    const float* wv   = (const float*)d_in[4];
    const float* wagg = (const float*)d_in[5];
    float* out = (float*)d_out;

    float *pWt, *pQ, *pK, *pV, *pS, *pm, *pil, *pHd;
    cudaGetSymbolAddress((void**)&pWt, g_Wt);
    cudaGetSymbolAddress((void**)&pQ,  g_Q);
    cudaGetSymbolAddress((void**)&pK,  g_K);
    cudaGetSymbolAddress((void**)&pV,  g_V);
    cudaGetSymbolAddress((void**)&pS,  g_S);
    cudaGetSymbolAddress((void**)&pm,  g_m);
    cudaGetSymbolAddress((void**)&pil, g_il);
    cudaGetSymbolAddress((void**)&pHd, g_Hd);

    // 1) transpose weights to [D, H*E]
    transpose_w<<<(H_ * D_ * E_) / 256, 256>>>(wq, wk, wv);

    // 2) QKV projections
    dim3 gProj(HE_ / 128, MR_ / 128);
    sgemm_nn_128<<<gProj, 256>>>(x, pWt,                pQ, MR_, HE_, D_);
    sgemm_nn_128<<<gProj, 256>>>(x, pWt + D_ * HE_,     pK, MR_, HE_, D_);
    sgemm_nn_128<<<gProj, 256>>>(x, pWt + 2 * D_ * HE_, pV, MR_, HE_, D_);

    // 3) scores^T
    scores_nt<<<dim3(S_ / 128, S_ / 128, B_ * H_), 256>>>(pK, pQ, pS);

    // 4) per-(bh,t) max + 1/sumexp
    softmax_stats<<<B_ * H_ * S_, 256>>>(pS, pm, pil);

    // 5) heads = attn @ v (fused exp-normalize)
    av_exp_tn<<<dim3(S_ / 128, B_ * H_), 128>>>(pS, pm, pil, pV, pHd);

    // 6) output = heads @ w_agg
    sgemm_nn_128<<<dim3(D_ / 128, MR_ / 128), 256>>>(pHd, wagg, out, MR_, D_, D_);
}